// round 1
// baseline (speedup 1.0000x reference)
#include <cuda_runtime.h>
#include <math.h>

#define NN 10000
#define NE 256000
#define HH 128
#define H2 256
#define H3 384
#define NR 20

// ---------------- scratch (static device globals; no allocation) ----------------
__device__ float g_x[NN * H3];                 // node inter-MLP output      (15.4 MB)
__device__ float g_filters[(size_t)NE * H3];   // per-edge filters           (393 MB)
__device__ float g_qmid[NN * HH];
__device__ float g_mumid[NN * 3 * HH];
__device__ float g_vnorm[NN * HH];
__device__ float g_inner[NN * HH];
__device__ float g_muw[NN * 3 * HH];
__device__ int   g_count[NN];
__device__ int   g_off[NN + 1];
__device__ int   g_cursor[NN];
__device__ int   g_elist[NE];

__device__ __forceinline__ float silu_f(float x) {
    return x / (1.0f + __expf(-x));
}

// ---------------- CSR build ----------------
__global__ void k_zero() {
    int i = blockIdx.x * blockDim.x + threadIdx.x;
    if (i < NN) g_count[i] = 0;
}

__global__ void k_count(const int* __restrict__ ei) {
    for (int e = blockIdx.x * blockDim.x + threadIdx.x; e < NE;
         e += gridDim.x * blockDim.x) {
        atomicAdd(&g_count[ei[e]], 1);   // ei[e] = target (row 0)
    }
}

__global__ __launch_bounds__(1024) void k_scan() {
    __shared__ int ps[1024];
    int tid = threadIdx.x;
    const int CH = (NN + 1023) / 1024;   // 10
    int base = tid * CH;
    int s = 0;
    for (int j = 0; j < CH; ++j) {
        int idx = base + j;
        if (idx < NN) s += g_count[idx];
    }
    ps[tid] = s;
    __syncthreads();
    for (int off = 1; off < 1024; off <<= 1) {
        int v = 0;
        if (tid >= off) v = ps[tid - off];
        __syncthreads();
        ps[tid] += v;
        __syncthreads();
    }
    int run = ps[tid] - s;               // exclusive prefix
    for (int j = 0; j < CH; ++j) {
        int idx = base + j;
        if (idx < NN) {
            g_off[idx] = run;
            g_cursor[idx] = run;
            run += g_count[idx];
        }
    }
    if (tid == 1023) g_off[NN] = ps[1023];
}

__global__ void k_fill(const int* __restrict__ ei) {
    for (int e = blockIdx.x * blockDim.x + threadIdx.x; e < NE;
         e += gridDim.x * blockDim.x) {
        int t = ei[e];
        int pos = atomicAdd(&g_cursor[t], 1);
        g_elist[pos] = e;
    }
}

// ---------------- node inter MLP: x = silu(q@W1+b1)@W2+b2  [N,384] ----------------
// block = 256 threads, 16 nodes/block. 4x4 register micro-tile.
__global__ __launch_bounds__(256) void k_node_mlp(
    const float* __restrict__ q,
    const float* __restrict__ W1, const float* __restrict__ b1,
    const float* __restrict__ W2, const float* __restrict__ b2)
{
    __shared__ float sq[16][HH];
    __shared__ float sh[16][H3];
    int tid = threadIdx.x;
    int n0 = blockIdx.x * 16;

    for (int i = tid; i < 16 * HH; i += 256)
        sq[i / HH][i % HH] = q[(n0 + i / HH) * HH + (i % HH)];
    __syncthreads();

    int rg = tid >> 6;       // 0..3  (warp-uniform)
    int cg = tid & 63;       // 0..63
    int r0 = rg * 4;

    // hidden = silu(q @ W1 + b1)   [16,384]
    for (int pass = 0; pass < 2; ++pass) {
        int c0 = cg * 4 + pass * 256;
        if (c0 >= H3) break;
        float acc[4][4] = {};
        for (int k = 0; k < HH; ++k) {
            float4 w = *reinterpret_cast<const float4*>(&W1[k * H3 + c0]);
            #pragma unroll
            for (int i = 0; i < 4; ++i) {
                float s = sq[r0 + i][k];
                acc[i][0] = fmaf(s, w.x, acc[i][0]);
                acc[i][1] = fmaf(s, w.y, acc[i][1]);
                acc[i][2] = fmaf(s, w.z, acc[i][2]);
                acc[i][3] = fmaf(s, w.w, acc[i][3]);
            }
        }
        #pragma unroll
        for (int i = 0; i < 4; ++i)
            #pragma unroll
            for (int j = 0; j < 4; ++j)
                sh[r0 + i][c0 + j] = silu_f(acc[i][j] + b1[c0 + j]);
    }
    __syncthreads();

    // x = hidden @ W2 + b2
    for (int pass = 0; pass < 2; ++pass) {
        int c0 = cg * 4 + pass * 256;
        if (c0 >= H3) break;
        float acc[4][4] = {};
        for (int k = 0; k < H3; ++k) {
            float4 w = *reinterpret_cast<const float4*>(&W2[k * H3 + c0]);
            #pragma unroll
            for (int i = 0; i < 4; ++i) {
                float s = sh[r0 + i][k];
                acc[i][0] = fmaf(s, w.x, acc[i][0]);
                acc[i][1] = fmaf(s, w.y, acc[i][1]);
                acc[i][2] = fmaf(s, w.z, acc[i][2]);
                acc[i][3] = fmaf(s, w.w, acc[i][3]);
            }
        }
        #pragma unroll
        for (int i = 0; i < 4; ++i)
            #pragma unroll
            for (int j = 0; j < 4; ++j)
                g_x[(n0 + r0 + i) * H3 + c0 + j] = acc[i][j] + b2[c0 + j];
    }
}

// ---------------- edge filter MLP: filters = (silu(rbf@Wf1+bf1)@Wf2+bf2)*cutoff ----------------
// block = 256 threads, 64 edges/block. Dominant GEMM (25 GFLOP).
__global__ __launch_bounds__(256) void k_edge_filter(
    const float* __restrict__ rbf, const float* __restrict__ cut,
    const float* __restrict__ Wf1, const float* __restrict__ bf1,
    const float* __restrict__ Wf2, const float* __restrict__ bf2)
{
    __shared__ float srb[64][NR];
    __shared__ float scut[64];
    __shared__ float sh[64][HH];
    int tid = threadIdx.x;
    int e0 = blockIdx.x * 64;

    for (int i = tid; i < 64 * NR; i += 256)
        srb[i / NR][i % NR] = rbf[(e0 + i / NR) * NR + (i % NR)];
    if (tid < 64) scut[tid] = cut[e0 + tid];
    __syncthreads();

    int rg = tid >> 4;   // 0..15
    int cg = tid & 15;   // 0..15
    int r0 = rg * 4;

    // hidden [64,128]
    for (int pass = 0; pass < 2; ++pass) {
        int c0 = cg * 4 + pass * 64;
        float acc[4][4] = {};
        for (int k = 0; k < NR; ++k) {
            float4 w = *reinterpret_cast<const float4*>(&Wf1[k * HH + c0]);
            #pragma unroll
            for (int i = 0; i < 4; ++i) {
                float s = srb[r0 + i][k];
                acc[i][0] = fmaf(s, w.x, acc[i][0]);
                acc[i][1] = fmaf(s, w.y, acc[i][1]);
                acc[i][2] = fmaf(s, w.z, acc[i][2]);
                acc[i][3] = fmaf(s, w.w, acc[i][3]);
            }
        }
        #pragma unroll
        for (int i = 0; i < 4; ++i)
            #pragma unroll
            for (int j = 0; j < 4; ++j)
                sh[r0 + i][c0 + j] = silu_f(acc[i][j] + bf1[c0 + j]);
    }
    __syncthreads();

    // filters [64,384]
    for (int pass = 0; pass < 6; ++pass) {
        int c0 = cg * 4 + pass * 64;
        float acc[4][4] = {};
        for (int k = 0; k < HH; ++k) {
            float4 w = *reinterpret_cast<const float4*>(&Wf2[k * H3 + c0]);
            #pragma unroll
            for (int i = 0; i < 4; ++i) {
                float s = sh[r0 + i][k];
                acc[i][0] = fmaf(s, w.x, acc[i][0]);
                acc[i][1] = fmaf(s, w.y, acc[i][1]);
                acc[i][2] = fmaf(s, w.z, acc[i][2]);
                acc[i][3] = fmaf(s, w.w, acc[i][3]);
            }
        }
        #pragma unroll
        for (int i = 0; i < 4; ++i) {
            float c = scut[r0 + i];
            size_t base = (size_t)(e0 + r0 + i) * H3 + c0;
            #pragma unroll
            for (int j = 0; j < 4; ++j)
                g_filters[base + j] = (acc[i][j] + bf2[c0 + j]) * c;
        }
    }
}

// ---------------- pull aggregation (CSR) -> qmid, mumid ----------------
__global__ __launch_bounds__(128) void k_aggregate(
    const float* __restrict__ q, const float* __restrict__ mu,
    const int* __restrict__ ei, const float* __restrict__ uv)
{
    int n = blockIdx.x;
    int h = threadIdx.x;
    int beg = g_off[n], end = g_off[n + 1];
    float qa = 0.f, m0 = 0.f, m1 = 0.f, m2 = 0.f;
    for (int i = beg; i < end; ++i) {
        int e = g_elist[i];
        int s = ei[NE + e];                       // source (row 1)
        const float* f = &g_filters[(size_t)e * H3];
        float fq = f[h], fr = f[HH + h], fm = f[2 * HH + h];
        const float* xs = &g_x[s * H3];
        float xq = xs[h] * fq;
        float xr = xs[HH + h] * fr;
        float xm = xs[2 * HH + h] * fm;
        float u0 = uv[e * 3 + 0], u1 = uv[e * 3 + 1], u2 = uv[e * 3 + 2];
        const float* ms = &mu[s * 3 * HH];
        qa += xq;
        m0 = fmaf(u0, xr, fmaf(ms[h],          xm, m0));
        m1 = fmaf(u1, xr, fmaf(ms[HH + h],     xm, m1));
        m2 = fmaf(u2, xr, fmaf(ms[2 * HH + h], xm, m2));
    }
    g_qmid[n * HH + h] = q[n * HH + h] + qa;
    g_mumid[n * 3 * HH + h]          = mu[n * 3 * HH + h] + m0;
    g_mumid[n * 3 * HH + HH + h]     = mu[n * 3 * HH + HH + h] + m1;
    g_mumid[n * 3 * HH + 2 * HH + h] = mu[n * 3 * HH + 2 * HH + h] + m2;
}

// ---------------- equivariant linear: vnorm, inner, mu_w ----------------
// block = 256 threads, 24 nodes/block.
__global__ __launch_bounds__(256) void k_equiv(const float* __restrict__ Wvec)
{
    __shared__ float sm[24][3 * HH];
    int tid = threadIdx.x;
    int n0 = blockIdx.x * 24;

    for (int i = tid; i < 24 * 3 * HH; i += 256) {
        int r = i / (3 * HH);
        int c = i % (3 * HH);
        int n = n0 + r;
        sm[r][c] = (n < NN) ? g_mumid[n * 3 * HH + c] : 0.f;
    }
    __syncthreads();

    for (int slot = tid; slot < 6 * HH; slot += 256) {  // 6 row-groups x 128 o
        int ng = slot >> 7;
        int o  = slot & 127;
        int r0 = ng * 4;
        float v[4][3] = {};
        float w[4][3] = {};
        for (int k = 0; k < HH; ++k) {
            float wv = Wvec[k * H2 + o];
            float ww = Wvec[k * H2 + HH + o];
            #pragma unroll
            for (int i = 0; i < 4; ++i)
                #pragma unroll
                for (int d = 0; d < 3; ++d) {
                    float m = sm[r0 + i][d * HH + k];
                    v[i][d] = fmaf(m, wv, v[i][d]);
                    w[i][d] = fmaf(m, ww, w[i][d]);
                }
        }
        #pragma unroll
        for (int i = 0; i < 4; ++i) {
            int n = n0 + r0 + i;
            if (n >= NN) break;
            float vn = sqrtf(v[i][0] * v[i][0] + v[i][1] * v[i][1] +
                             v[i][2] * v[i][2] + 1e-8f);
            float in = v[i][0] * w[i][0] + v[i][1] * w[i][1] + v[i][2] * w[i][2];
            g_vnorm[n * HH + o] = vn;
            g_inner[n * HH + o] = in;
            g_muw[n * 3 * HH + o]          = w[i][0];
            g_muw[n * 3 * HH + HH + o]     = w[i][1];
            g_muw[n * 3 * HH + 2 * HH + o] = w[i][2];
        }
    }
}

// ---------------- scalar mix MLP + final update ----------------
// block = 256 threads, 16 nodes/block (static smem <= 48KB).
__global__ __launch_bounds__(256) void k_mix(
    const float* __restrict__ Wm1, const float* __restrict__ bm1,
    const float* __restrict__ Wm2, const float* __restrict__ bm2,
    float* __restrict__ qout, float* __restrict__ muout)
{
    __shared__ float sin_[16][H2];
    __shared__ float shid[16][H3];
    int tid = threadIdx.x;
    int n0 = blockIdx.x * 16;

    for (int i = tid; i < 16 * H2; i += 256) {
        int r = i >> 8;
        int c = i & 255;
        int n = n0 + r;
        float v = 0.f;
        if (n < NN) v = (c < HH) ? g_qmid[n * HH + c] : g_vnorm[n * HH + (c - HH)];
        sin_[r][c] = v;
    }
    __syncthreads();

    int rg = tid >> 6;   // 0..3
    int cg = tid & 63;   // 0..63
    int r0 = rg * 4;

    // hidden = silu(scalar_input @ Wm1 + bm1)   [16,384]
    for (int pass = 0; pass < 2; ++pass) {
        int c0 = cg * 4 + pass * 256;
        if (c0 >= H3) break;
        float acc[4][4] = {};
        for (int k = 0; k < H2; ++k) {
            float4 w = *reinterpret_cast<const float4*>(&Wm1[k * H3 + c0]);
            #pragma unroll
            for (int i = 0; i < 4; ++i) {
                float s = sin_[r0 + i][k];
                acc[i][0] = fmaf(s, w.x, acc[i][0]);
                acc[i][1] = fmaf(s, w.y, acc[i][1]);
                acc[i][2] = fmaf(s, w.z, acc[i][2]);
                acc[i][3] = fmaf(s, w.w, acc[i][3]);
            }
        }
        #pragma unroll
        for (int i = 0; i < 4; ++i)
            #pragma unroll
            for (int j = 0; j < 4; ++j)
                shid[r0 + i][c0 + j] = silu_f(acc[i][j] + bm1[c0 + j]);
    }
    __syncthreads();

    // delta = hidden @ Wm2 + bm2 (3 columns per channel), then final update
    for (int slot = tid; slot < 4 * HH; slot += 256) {  // 4 row-groups x 128 o
        int ng = slot >> 7;
        int o  = slot & 127;
        int rr0 = ng * 4;
        float aq[4] = {}, as[4] = {}, am[4] = {};
        for (int k = 0; k < H3; ++k) {
            float wq = Wm2[k * H3 + o];
            float ws = Wm2[k * H3 + HH + o];
            float wm = Wm2[k * H3 + 2 * HH + o];
            #pragma unroll
            for (int i = 0; i < 4; ++i) {
                float hv = shid[rr0 + i][k];
                aq[i] = fmaf(hv, wq, aq[i]);
                as[i] = fmaf(hv, ws, as[i]);
                am[i] = fmaf(hv, wm, am[i]);
            }
        }
        #pragma unroll
        for (int i = 0; i < 4; ++i) {
            int n = n0 + rr0 + i;
            if (n >= NN) break;
            float dq  = aq[i] + bm2[o];
            float dms = as[i] + bm2[HH + o];
            float dqm = am[i] + bm2[2 * HH + o];
            qout[n * HH + o] = g_qmid[n * HH + o] + dq + dqm * g_inner[n * HH + o];
            #pragma unroll
            for (int d = 0; d < 3; ++d) {
                int idx = n * 3 * HH + d * HH + o;
                muout[idx] = g_mumid[idx] + g_muw[idx] * dms;
            }
        }
    }
}

// ---------------- launch ----------------
extern "C" void kernel_launch(void* const* d_in, const int* in_sizes, int n_in,
                              void* d_out, int out_size)
{
    const float* q   = (const float*)d_in[0];
    const float* mu  = (const float*)d_in[1];
    const int*   ei  = (const int*)d_in[2];
    const float* rbf = (const float*)d_in[3];
    const float* uv  = (const float*)d_in[4];
    const float* cut = (const float*)d_in[5];
    const float* Wi1 = (const float*)d_in[6];
    const float* bi1 = (const float*)d_in[7];
    const float* Wi2 = (const float*)d_in[8];
    const float* bi2 = (const float*)d_in[9];
    const float* Wf1 = (const float*)d_in[10];
    const float* bf1 = (const float*)d_in[11];
    const float* Wf2 = (const float*)d_in[12];
    const float* bf2 = (const float*)d_in[13];
    const float* Wv  = (const float*)d_in[14];
    const float* Wm1 = (const float*)d_in[15];
    const float* bm1 = (const float*)d_in[16];
    const float* Wm2 = (const float*)d_in[17];
    const float* bm2 = (const float*)d_in[18];

    float* qout  = (float*)d_out;
    float* muout = qout + (size_t)NN * HH;

    // CSR build
    k_zero<<<(NN + 255) / 256, 256>>>();
    k_count<<<512, 256>>>(ei);
    k_scan<<<1, 1024>>>();
    k_fill<<<512, 256>>>(ei);

    // dense stages
    k_node_mlp<<<NN / 16, 256>>>(q, Wi1, bi1, Wi2, bi2);
    k_edge_filter<<<NE / 64, 256>>>(rbf, cut, Wf1, bf1, Wf2, bf2);

    // message aggregation
    k_aggregate<<<NN, 128>>>(q, mu, ei, uv);

    // mixing
    k_equiv<<<(NN + 23) / 24, 256>>>(Wv);
    k_mix<<<(NN + 15) / 16, 256>>>(Wm1, bm1, Wm2, bm2, qout, muout);
}